// round 2
// baseline (speedup 1.0000x reference)
#include <cuda_runtime.h>
#include <math.h>

#define CB  128
#define CIN 256
#define NSP 4096
#define NB  4

// Scratch (static device globals — allocation-free per harness rules)
__device__ float g_T[(size_t)NB * CB * NSP];          // conv theta out, (128,4096) per batch
__device__ float g_P[(size_t)NB * CB * NSP];          // conv phi out
__device__ float g_G[(size_t)NB * CB * NSP];          // conv g out
__device__ float g_Y[(size_t)NB * CB * NSP];          // attention output, (4096,128) per batch
__device__ float g_L[NB * NSP];                       // per-column logsumexp: max + log(sum)
__device__ float g_S[(size_t)NB * NSP * NSP];         // scores, 256 MB

// ---------------------------------------------------------------------------
// Kernel 1: T/P/G 1x1 convs as GEMM: C(128,4096) = W(128,256) @ X(256,4096) + bias
// grid (32, 1, 12): z = b*3 + mat
// ---------------------------------------------------------------------------
__global__ __launch_bounds__(256, 2) void conv_tpg_kernel(
    const float* __restrict__ x,
    const float* __restrict__ tw, const float* __restrict__ tbias,
    const float* __restrict__ pw, const float* __restrict__ pbias,
    const float* __restrict__ gw, const float* __restrict__ gbias)
{
    int z = blockIdx.z;
    int b = z / 3, mat = z - b * 3;
    const float* W    = (mat == 0) ? tw    : (mat == 1) ? pw    : gw;
    const float* bias = (mat == 0) ? tbias : (mat == 1) ? pbias : gbias;
    float* Cout = ((mat == 0) ? g_T : (mat == 1) ? g_P : g_G) + (size_t)b * CB * NSP;
    const float* Bx = x + (size_t)b * CIN * NSP;

    __shared__ float As[8][132];
    __shared__ float Bs[8][128];
    int tid  = threadIdx.x;
    int aRow = tid >> 1, aCol = (tid & 1) << 2;
    int bRow = tid >> 5, bCol = (tid & 31) << 2;
    int ty = tid >> 4, tx = tid & 15;
    int colBase = blockIdx.x << 7;

    float acc[8][8];
#pragma unroll
    for (int i = 0; i < 8; i++)
#pragma unroll
        for (int j = 0; j < 8; j++) acc[i][j] = 0.f;

    for (int k0 = 0; k0 < CIN; k0 += 8) {
        float4 av = *(const float4*)(W + (size_t)aRow * CIN + k0 + aCol);
        As[aCol + 0][aRow] = av.x;
        As[aCol + 1][aRow] = av.y;
        As[aCol + 2][aRow] = av.z;
        As[aCol + 3][aRow] = av.w;
        *(float4*)&Bs[bRow][bCol] =
            *(const float4*)(Bx + (size_t)(k0 + bRow) * NSP + colBase + bCol);
        __syncthreads();
#pragma unroll
        for (int k = 0; k < 8; k++) {
            float ra[8], rb[8];
            *(float4*)(ra)     = *(const float4*)&As[k][ty << 2];
            *(float4*)(ra + 4) = *(const float4*)&As[k][64 + (ty << 2)];
            *(float4*)(rb)     = *(const float4*)&Bs[k][tx << 2];
            *(float4*)(rb + 4) = *(const float4*)&Bs[k][64 + (tx << 2)];
#pragma unroll
            for (int i = 0; i < 8; i++)
#pragma unroll
                for (int j = 0; j < 8; j++)
                    acc[i][j] = fmaf(ra[i], rb[j], acc[i][j]);
        }
        __syncthreads();
    }
#pragma unroll
    for (int ih = 0; ih < 2; ih++)
#pragma unroll
        for (int i = 0; i < 4; i++) {
            int row = (ih << 6) + (ty << 2) + i;
            float bv = bias[row];
#pragma unroll
            for (int jh = 0; jh < 2; jh++) {
                float4 v;
                v.x = acc[ih * 4 + i][jh * 4 + 0] + bv;
                v.y = acc[ih * 4 + i][jh * 4 + 1] + bv;
                v.z = acc[ih * 4 + i][jh * 4 + 2] + bv;
                v.w = acc[ih * 4 + i][jh * 4 + 3] + bv;
                *(float4*)(Cout + (size_t)row * NSP + colBase + (jh << 6) + (tx << 2)) = v;
            }
        }
}

// ---------------------------------------------------------------------------
// Kernel 2: scores S(4096,4096) = Tview(4096,128) @ P(128,4096)
// Tview is just the flat T buffer with lda=128. grid (32, 32, 4)
// ---------------------------------------------------------------------------
__global__ __launch_bounds__(256, 2) void scores_kernel()
{
    int b = blockIdx.z;
    const float* A  = g_T + (size_t)b * CB * NSP;    // (4096,128) lda=128
    const float* Bp = g_P + (size_t)b * CB * NSP;    // (128,4096) ldb=4096
    float* C = g_S + (size_t)b * NSP * NSP;

    __shared__ float As[8][132];
    __shared__ float Bs[8][128];
    int tid  = threadIdx.x;
    int aRow = tid >> 1, aCol = (tid & 1) << 2;
    int bRow = tid >> 5, bCol = (tid & 31) << 2;
    int ty = tid >> 4, tx = tid & 15;
    int rowBase = blockIdx.y << 7;
    int colBase = blockIdx.x << 7;

    float acc[8][8];
#pragma unroll
    for (int i = 0; i < 8; i++)
#pragma unroll
        for (int j = 0; j < 8; j++) acc[i][j] = 0.f;

    for (int k0 = 0; k0 < CB; k0 += 8) {
        float4 av = *(const float4*)(A + (size_t)(rowBase + aRow) * CB + k0 + aCol);
        As[aCol + 0][aRow] = av.x;
        As[aCol + 1][aRow] = av.y;
        As[aCol + 2][aRow] = av.z;
        As[aCol + 3][aRow] = av.w;
        *(float4*)&Bs[bRow][bCol] =
            *(const float4*)(Bp + (size_t)(k0 + bRow) * NSP + colBase + bCol);
        __syncthreads();
#pragma unroll
        for (int k = 0; k < 8; k++) {
            float ra[8], rb[8];
            *(float4*)(ra)     = *(const float4*)&As[k][ty << 2];
            *(float4*)(ra + 4) = *(const float4*)&As[k][64 + (ty << 2)];
            *(float4*)(rb)     = *(const float4*)&Bs[k][tx << 2];
            *(float4*)(rb + 4) = *(const float4*)&Bs[k][64 + (tx << 2)];
#pragma unroll
            for (int i = 0; i < 8; i++)
#pragma unroll
                for (int j = 0; j < 8; j++)
                    acc[i][j] = fmaf(ra[i], rb[j], acc[i][j]);
        }
        __syncthreads();
    }
#pragma unroll
    for (int ih = 0; ih < 2; ih++)
#pragma unroll
        for (int i = 0; i < 4; i++) {
            int row = rowBase + (ih << 6) + (ty << 2) + i;
#pragma unroll
            for (int jh = 0; jh < 2; jh++) {
                float4 v;
                v.x = acc[ih * 4 + i][jh * 4 + 0];
                v.y = acc[ih * 4 + i][jh * 4 + 1];
                v.z = acc[ih * 4 + i][jh * 4 + 2];
                v.w = acc[ih * 4 + i][jh * 4 + 3];
                *(float4*)(C + (size_t)row * NSP + colBase + (jh << 6) + (tx << 2)) = v;
            }
        }
}

// ---------------------------------------------------------------------------
// Kernel 3: column-wise online softmax stats: L[b,m] = max_n S + log(sum_n exp)
// grid (32, 4), 512 threads: 128 columns per block, 4 row-lanes per column
// ---------------------------------------------------------------------------
__global__ __launch_bounds__(512) void colsoftmax_kernel()
{
    int b = blockIdx.y;
    int mBase = blockIdx.x << 7;
    int tid  = threadIdx.x;
    int mOff = tid & 127;
    int r0   = tid >> 7;
    const float* S = g_S + (size_t)b * NSP * NSP + mBase + mOff;

    float mx = -1e30f, sum = 0.f;
    for (int n = r0; n < NSP; n += 4) {
        float v = S[(size_t)n * NSP];
        if (v > mx) {
            sum = sum * __expf(mx - v) + 1.f;
            mx = v;
        } else {
            sum += __expf(v - mx);
        }
    }
    __shared__ float sM[4][128];
    __shared__ float sS[4][128];
    sM[r0][mOff] = mx;
    sS[r0][mOff] = sum;
    __syncthreads();
    if (r0 == 0) {
        float M = sM[0][mOff], Z = sS[0][mOff];
#pragma unroll
        for (int r = 1; r < 4; r++) {
            float m2 = sM[r][mOff], s2 = sS[r][mOff];
            float nm = fmaxf(M, m2);
            Z = Z * __expf(M - nm) + s2 * __expf(m2 - nm);
            M = nm;
        }
        g_L[b * NSP + mBase + mOff] = M + logf(Z);
    }
}

// ---------------------------------------------------------------------------
// Kernel 4: Y(4096,128) = exp(S - L[m]) @ Gview(4096,128)
// BM=64, BN=128(full), BK=8, 4x8 per thread. grid (1, 64, 4)
// ---------------------------------------------------------------------------
__global__ __launch_bounds__(256, 2) void y_kernel()
{
    int b = blockIdx.z;
    const float* S  = g_S + (size_t)b * NSP * NSP;
    const float* L  = g_L + b * NSP;
    const float* Gm = g_G + (size_t)b * CB * NSP;    // (4096,128) ldb=128
    float* Y = g_Y + (size_t)b * CB * NSP;

    __shared__ float As[8][68];
    __shared__ float Bs[8][128];
    int tid  = threadIdx.x;
    int aRow = tid >> 2, aCol = (tid & 3) << 1;
    int bRow = tid >> 5, bCol = (tid & 31) << 2;
    int ty = tid >> 4, tx = tid & 15;
    int rowBase = blockIdx.y << 6;

    float acc[4][8];
#pragma unroll
    for (int i = 0; i < 4; i++)
#pragma unroll
        for (int j = 0; j < 8; j++) acc[i][j] = 0.f;

    for (int k0 = 0; k0 < NSP; k0 += 8) {
        float2 av = *(const float2*)(S + (size_t)(rowBase + aRow) * NSP + k0 + aCol);
        As[aCol + 0][aRow] = __expf(av.x - L[k0 + aCol]);
        As[aCol + 1][aRow] = __expf(av.y - L[k0 + aCol + 1]);
        *(float4*)&Bs[bRow][bCol] =
            *(const float4*)(Gm + (size_t)(k0 + bRow) * CB + bCol);
        __syncthreads();
#pragma unroll
        for (int k = 0; k < 8; k++) {
            float ra[4], rb[8];
            *(float4*)(ra)     = *(const float4*)&As[k][ty << 2];
            *(float4*)(rb)     = *(const float4*)&Bs[k][tx << 2];
            *(float4*)(rb + 4) = *(const float4*)&Bs[k][64 + (tx << 2)];
#pragma unroll
            for (int i = 0; i < 4; i++)
#pragma unroll
                for (int j = 0; j < 8; j++)
                    acc[i][j] = fmaf(ra[i], rb[j], acc[i][j]);
        }
        __syncthreads();
    }
#pragma unroll
    for (int i = 0; i < 4; i++) {
        int row = rowBase + (ty << 2) + i;
#pragma unroll
        for (int jh = 0; jh < 2; jh++) {
            float4 v;
            v.x = acc[i][jh * 4 + 0];
            v.y = acc[i][jh * 4 + 1];
            v.z = acc[i][jh * 4 + 2];
            v.w = acc[i][jh * 4 + 3];
            *(float4*)(Y + (size_t)row * CB + (jh << 6) + (tx << 2)) = v;
        }
    }
}

// ---------------------------------------------------------------------------
// Kernel 5: Out(256,4096) = W_w(256,128) @ Yview(128,4096) + W_b + x  (residual)
// grid (32, 2, 4)
// ---------------------------------------------------------------------------
__global__ __launch_bounds__(256, 2) void out_kernel(
    const float* __restrict__ x,
    const float* __restrict__ Ww, const float* __restrict__ Wb,
    float* __restrict__ out)
{
    int b = blockIdx.z;
    const float* Byc = g_Y + (size_t)b * CB * NSP;   // (128,4096) ldb=4096
    const float* xb  = x + (size_t)b * CIN * NSP;
    float* Cb_ = out + (size_t)b * CIN * NSP;

    __shared__ float As[8][132];
    __shared__ float Bs[8][128];
    int tid  = threadIdx.x;
    int aRow = tid >> 1, aCol = (tid & 1) << 2;
    int bRow = tid >> 5, bCol = (tid & 31) << 2;
    int ty = tid >> 4, tx = tid & 15;
    int rowBase = blockIdx.y << 7;
    int colBase = blockIdx.x << 7;

    float acc[8][8];
#pragma unroll
    for (int i = 0; i < 8; i++)
#pragma unroll
        for (int j = 0; j < 8; j++) acc[i][j] = 0.f;

    for (int k0 = 0; k0 < CB; k0 += 8) {
        float4 av = *(const float4*)(Ww + (size_t)(rowBase + aRow) * CB + k0 + aCol);
        As[aCol + 0][aRow] = av.x;
        As[aCol + 1][aRow] = av.y;
        As[aCol + 2][aRow] = av.z;
        As[aCol + 3][aRow] = av.w;
        *(float4*)&Bs[bRow][bCol] =
            *(const float4*)(Byc + (size_t)(k0 + bRow) * NSP + colBase + bCol);
        __syncthreads();
#pragma unroll
        for (int k = 0; k < 8; k++) {
            float ra[8], rb[8];
            *(float4*)(ra)     = *(const float4*)&As[k][ty << 2];
            *(float4*)(ra + 4) = *(const float4*)&As[k][64 + (ty << 2)];
            *(float4*)(rb)     = *(const float4*)&Bs[k][tx << 2];
            *(float4*)(rb + 4) = *(const float4*)&Bs[k][64 + (tx << 2)];
#pragma unroll
            for (int i = 0; i < 8; i++)
#pragma unroll
                for (int j = 0; j < 8; j++)
                    acc[i][j] = fmaf(ra[i], rb[j], acc[i][j]);
        }
        __syncthreads();
    }
#pragma unroll
    for (int ih = 0; ih < 2; ih++)
#pragma unroll
        for (int i = 0; i < 4; i++) {
            int row = rowBase + (ih << 6) + (ty << 2) + i;
            float bv = Wb[row];
#pragma unroll
            for (int jh = 0; jh < 2; jh++) {
                int col = colBase + (jh << 6) + (tx << 2);
                float4 xv = *(const float4*)(xb + (size_t)row * NSP + col);
                float4 v;
                v.x = acc[ih * 4 + i][jh * 4 + 0] + bv + xv.x;
                v.y = acc[ih * 4 + i][jh * 4 + 1] + bv + xv.y;
                v.z = acc[ih * 4 + i][jh * 4 + 2] + bv + xv.z;
                v.w = acc[ih * 4 + i][jh * 4 + 3] + bv + xv.w;
                *(float4*)(Cb_ + (size_t)row * NSP + col) = v;
            }
        }
}

// ---------------------------------------------------------------------------
extern "C" void kernel_launch(void* const* d_in, const int* in_sizes, int n_in,
                              void* d_out, int out_size)
{
    const float* x  = (const float*)d_in[0];
    const float* tw = (const float*)d_in[1];
    const float* tb = (const float*)d_in[2];
    const float* pw = (const float*)d_in[3];
    const float* pb = (const float*)d_in[4];
    const float* gw = (const float*)d_in[5];
    const float* gb = (const float*)d_in[6];
    const float* Ww = (const float*)d_in[7];
    const float* Wb = (const float*)d_in[8];
    float* out = (float*)d_out;

    conv_tpg_kernel<<<dim3(32, 1, 12), 256>>>(x, tw, tb, pw, pb, gw, gb);
    scores_kernel<<<dim3(32, 32, 4), 256>>>();
    colsoftmax_kernel<<<dim3(32, 4), 512>>>();
    y_kernel<<<dim3(1, 64, 4), 256>>>();
    out_kernel<<<dim3(32, 2, 4), 256>>>(x, Ww, Wb, out);
}

// round 4
// speedup vs baseline: 1.4392x; 1.4392x over previous
#include <cuda_runtime.h>
#include <math.h>

#define CB  128
#define CIN 256
#define NSP 4096
#define NB  4
#define KSPLIT 8
#define KCH (NSP / KSPLIT)   // 512

typedef unsigned long long u64;

__device__ __forceinline__ u64 pk2(float a, float b) {
    u64 r; asm("mov.b64 %0, {%1, %2};" : "=l"(r) : "f"(a), "f"(b)); return r;
}
__device__ __forceinline__ void upk2(u64 v, float& a, float& b) {
    asm("mov.b64 {%0, %1}, %2;" : "=f"(a), "=f"(b) : "l"(v));
}
__device__ __forceinline__ u64 fma2(u64 a, u64 b, u64 c) {
    u64 d; asm("fma.rn.f32x2 %0, %1, %2, %3;" : "=l"(d) : "l"(a), "l"(b), "l"(c)); return d;
}

// Scratch (static device globals — allocation-free per harness rules)
__device__ float g_T[(size_t)NB * CB * NSP];
__device__ float g_P[(size_t)NB * CB * NSP];
__device__ float g_G[(size_t)NB * CB * NSP];
__device__ float g_Y[(size_t)NB * CB * NSP];
__device__ float g_S[(size_t)NB * NSP * NSP];        // holds exp(scores)
__device__ float g_Zp[NB * 32 * NSP];                // per-rowtile column sums of exp
__device__ float g_Zr[NB * NSP];                     // 1/Z per column
__device__ float g_Yp[(size_t)KSPLIT * NB * NSP * CB];  // split-K partials

// ---------------------------------------------------------------------------
// Kernel 1: T/P/G 1x1 convs: C(128,4096) = W(128,256) @ X(256,4096) + bias
// grid (32, 1, 12)
// ---------------------------------------------------------------------------
__global__ __launch_bounds__(256, 2) void conv_tpg_kernel(
    const float* __restrict__ x,
    const float* __restrict__ tw, const float* __restrict__ tbias,
    const float* __restrict__ pw, const float* __restrict__ pbias,
    const float* __restrict__ gw, const float* __restrict__ gbias)
{
    int z = blockIdx.z;
    int b = z / 3, mat = z - b * 3;
    const float* W    = (mat == 0) ? tw    : (mat == 1) ? pw    : gw;
    const float* bias = (mat == 0) ? tbias : (mat == 1) ? pbias : gbias;
    float* Cout = ((mat == 0) ? g_T : (mat == 1) ? g_P : g_G) + (size_t)b * CB * NSP;
    const float* Bx = x + (size_t)b * CIN * NSP;

    __shared__ __align__(16) float As[8][132];
    __shared__ __align__(16) float Bs[8][128];
    int tid  = threadIdx.x;
    int aRow = tid >> 1, aCol = (tid & 1) << 2;
    int bRow = tid >> 5, bCol = (tid & 31) << 2;
    int ty = tid >> 4, tx = tid & 15;
    int colBase = blockIdx.x << 7;

    u64 acc[8][4];
#pragma unroll
    for (int i = 0; i < 8; i++)
#pragma unroll
        for (int jp = 0; jp < 4; jp++) acc[i][jp] = pk2(0.f, 0.f);

    for (int k0 = 0; k0 < CIN; k0 += 8) {
        float4 av = *(const float4*)(W + (size_t)aRow * CIN + k0 + aCol);
        As[aCol + 0][aRow] = av.x;
        As[aCol + 1][aRow] = av.y;
        As[aCol + 2][aRow] = av.z;
        As[aCol + 3][aRow] = av.w;
        *(float4*)&Bs[bRow][bCol] =
            *(const float4*)(Bx + (size_t)(k0 + bRow) * NSP + colBase + bCol);
        __syncthreads();
#pragma unroll
        for (int k = 0; k < 8; k++) {
            float ra[8];
            *(float4*)(ra)     = *(const float4*)&As[k][ty << 2];
            *(float4*)(ra + 4) = *(const float4*)&As[k][64 + (ty << 2)];
            const u64* bp0 = (const u64*)&Bs[k][tx << 2];
            const u64* bp1 = (const u64*)&Bs[k][64 + (tx << 2)];
            u64 rb[4] = {bp0[0], bp0[1], bp1[0], bp1[1]};
#pragma unroll
            for (int i = 0; i < 8; i++) {
                u64 aa = pk2(ra[i], ra[i]);
#pragma unroll
                for (int jp = 0; jp < 4; jp++)
                    acc[i][jp] = fma2(aa, rb[jp], acc[i][jp]);
            }
        }
        __syncthreads();
    }
#pragma unroll
    for (int i = 0; i < 8; i++) {
        int row = ((i >> 2) << 6) + (ty << 2) + (i & 3);
        float bv = bias[row];
#pragma unroll
        for (int jh = 0; jh < 2; jh++) {
            float4 v;
            upk2(acc[i][2 * jh],     v.x, v.y);
            upk2(acc[i][2 * jh + 1], v.z, v.w);
            v.x += bv; v.y += bv; v.z += bv; v.w += bv;
            *(float4*)(Cout + (size_t)row * NSP + colBase + (jh << 6) + (tx << 2)) = v;
        }
    }
}

// ---------------------------------------------------------------------------
// Kernel 2: expS(4096,4096) = exp( Tview(4096,128) @ P(128,4096) )
// plus per-row-tile column sums of exp into g_Zp. grid (32, 32, 4)
// ---------------------------------------------------------------------------
__global__ __launch_bounds__(256, 2) void scores_kernel()
{
    int b = blockIdx.z;
    const float* A  = g_T + (size_t)b * CB * NSP;    // (4096,128) lda=128
    const float* Bp = g_P + (size_t)b * CB * NSP;    // (128,4096) ldb=4096
    float* C = g_S + (size_t)b * NSP * NSP;

    __shared__ __align__(16) float As[8][132];
    __shared__ __align__(16) float Bs[8][128];
    __shared__ float sCol[16][128];
    int tid  = threadIdx.x;
    int aRow = tid >> 1, aCol = (tid & 1) << 2;
    int bRow = tid >> 5, bCol = (tid & 31) << 2;
    int ty = tid >> 4, tx = tid & 15;
    int rowBase = blockIdx.y << 7;
    int colBase = blockIdx.x << 7;

    u64 acc[8][4];
#pragma unroll
    for (int i = 0; i < 8; i++)
#pragma unroll
        for (int jp = 0; jp < 4; jp++) acc[i][jp] = pk2(0.f, 0.f);

    for (int k0 = 0; k0 < CB; k0 += 8) {
        float4 av = *(const float4*)(A + (size_t)(rowBase + aRow) * CB + k0 + aCol);
        As[aCol + 0][aRow] = av.x;
        As[aCol + 1][aRow] = av.y;
        As[aCol + 2][aRow] = av.z;
        As[aCol + 3][aRow] = av.w;
        *(float4*)&Bs[bRow][bCol] =
            *(const float4*)(Bp + (size_t)(k0 + bRow) * NSP + colBase + bCol);
        __syncthreads();
#pragma unroll
        for (int k = 0; k < 8; k++) {
            float ra[8];
            *(float4*)(ra)     = *(const float4*)&As[k][ty << 2];
            *(float4*)(ra + 4) = *(const float4*)&As[k][64 + (ty << 2)];
            const u64* bp0 = (const u64*)&Bs[k][tx << 2];
            const u64* bp1 = (const u64*)&Bs[k][64 + (tx << 2)];
            u64 rb[4] = {bp0[0], bp0[1], bp1[0], bp1[1]};
#pragma unroll
            for (int i = 0; i < 8; i++) {
                u64 aa = pk2(ra[i], ra[i]);
#pragma unroll
                for (int jp = 0; jp < 4; jp++)
                    acc[i][jp] = fma2(aa, rb[jp], acc[i][jp]);
            }
        }
        __syncthreads();
    }

    // Epilogue: exp(), write expS, per-thread column partial sums
    float csum[8];
#pragma unroll
    for (int j = 0; j < 8; j++) csum[j] = 0.f;
#pragma unroll
    for (int i = 0; i < 8; i++) {
        int row = rowBase + ((i >> 2) << 6) + (ty << 2) + (i & 3);
#pragma unroll
        for (int jh = 0; jh < 2; jh++) {
            float4 v;
            upk2(acc[i][2 * jh],     v.x, v.y);
            upk2(acc[i][2 * jh + 1], v.z, v.w);
            v.x = __expf(v.x); v.y = __expf(v.y);
            v.z = __expf(v.z); v.w = __expf(v.w);
            csum[jh * 4 + 0] += v.x;
            csum[jh * 4 + 1] += v.y;
            csum[jh * 4 + 2] += v.z;
            csum[jh * 4 + 3] += v.w;
            *(float4*)(C + (size_t)row * NSP + colBase + (jh << 6) + (tx << 2)) = v;
        }
    }
#pragma unroll
    for (int j = 0; j < 8; j++)
        sCol[ty][((j >> 2) << 6) + (tx << 2) + (j & 3)] = csum[j];
    __syncthreads();
    if (tid < 128) {
        float s = 0.f;
#pragma unroll
        for (int r = 0; r < 16; r++) s += sCol[r][tid];
        g_Zp[(b * 32 + blockIdx.y) * NSP + colBase + tid] = s;
    }
}

// ---------------------------------------------------------------------------
// Kernel 3: 1/Z per column (fixed-order, deterministic). grid (64), 256 thr
// ---------------------------------------------------------------------------
__global__ __launch_bounds__(256) void zreduce_kernel()
{
    int t = blockIdx.x * 256 + threadIdx.x;       // 0 .. NB*NSP-1
    int b = t >> 12, m = t & (NSP - 1);
    float s = 0.f;
#pragma unroll 8
    for (int r = 0; r < 32; r++) s += g_Zp[(b * 32 + r) * NSP + m];
    g_Zr[t] = 1.0f / s;
}

// ---------------------------------------------------------------------------
// Kernel 4: split-K attention GEMM partials:
// Yp[ks] = expS(4096, Kchunk) @ (Gview * (1/Z)) (Kchunk,128). grid (8, 32, 4)
// ---------------------------------------------------------------------------
__global__ __launch_bounds__(256, 2) void y_kernel()
{
    int ks = blockIdx.x;
    int b  = blockIdx.z;
    const float* S  = g_S + (size_t)b * NSP * NSP;
    const float* Gm = g_G + (size_t)b * CB * NSP;    // (4096,128) as flat view, ld=128
    const float* Zr = g_Zr + b * NSP;
    float* Cp = g_Yp + (size_t)ks * NB * NSP * CB + (size_t)b * NSP * CB;

    __shared__ __align__(16) float As[8][132];
    __shared__ __align__(16) float Bs[8][128];
    int tid  = threadIdx.x;
    int aRow = tid >> 1, aCol = (tid & 1) << 2;
    int bRow = tid >> 5, bCol = (tid & 31) << 2;
    int ty = tid >> 4, tx = tid & 15;
    int rowBase = blockIdx.y << 7;

    u64 acc[8][4];
#pragma unroll
    for (int i = 0; i < 8; i++)
#pragma unroll
        for (int jp = 0; jp < 4; jp++) acc[i][jp] = pk2(0.f, 0.f);

    int kEnd = (ks + 1) * KCH;
    for (int k0 = ks * KCH; k0 < kEnd; k0 += 8) {
        float4 av = *(const float4*)(S + (size_t)(rowBase + aRow) * NSP + k0 + aCol);
        As[aCol + 0][aRow] = av.x;
        As[aCol + 1][aRow] = av.y;
        As[aCol + 2][aRow] = av.z;
        As[aCol + 3][aRow] = av.w;
        float zr = Zr[k0 + bRow];
        float4 gv = *(const float4*)(Gm + (size_t)(k0 + bRow) * CB + bCol);
        gv.x *= zr; gv.y *= zr; gv.z *= zr; gv.w *= zr;
        *(float4*)&Bs[bRow][bCol] = gv;
        __syncthreads();
#pragma unroll
        for (int k = 0; k < 8; k++) {
            float ra[8];
            *(float4*)(ra)     = *(const float4*)&As[k][ty << 2];
            *(float4*)(ra + 4) = *(const float4*)&As[k][64 + (ty << 2)];
            const u64* bp0 = (const u64*)&Bs[k][tx << 2];
            const u64* bp1 = (const u64*)&Bs[k][64 + (tx << 2)];
            u64 rb[4] = {bp0[0], bp0[1], bp1[0], bp1[1]};
#pragma unroll
            for (int i = 0; i < 8; i++) {
                u64 aa = pk2(ra[i], ra[i]);
#pragma unroll
                for (int jp = 0; jp < 4; jp++)
                    acc[i][jp] = fma2(aa, rb[jp], acc[i][jp]);
            }
        }
        __syncthreads();
    }
#pragma unroll
    for (int i = 0; i < 8; i++) {
        int row = rowBase + ((i >> 2) << 6) + (ty << 2) + (i & 3);
#pragma unroll
        for (int jh = 0; jh < 2; jh++) {
            float4 v;
            upk2(acc[i][2 * jh],     v.x, v.y);
            upk2(acc[i][2 * jh + 1], v.z, v.w);
            *(float4*)(Cp + (size_t)row * CB + (jh << 6) + (tx << 2)) = v;
        }
    }
}

// ---------------------------------------------------------------------------
// Kernel 5: reduce split-K partials (fixed order). grid (2048), 256 thr
// ---------------------------------------------------------------------------
__global__ __launch_bounds__(256) void yreduce_kernel()
{
    size_t idx = ((size_t)blockIdx.x * 256 + threadIdx.x) * 4;
    const size_t stride = (size_t)NB * NSP * CB;
    float4 s = *(const float4*)&g_Yp[idx];
#pragma unroll
    for (int r = 1; r < KSPLIT; r++) {
        float4 t = *(const float4*)&g_Yp[(size_t)r * stride + idx];
        s.x += t.x; s.y += t.y; s.z += t.z; s.w += t.w;
    }
    *(float4*)&g_Y[idx] = s;
}

// ---------------------------------------------------------------------------
// Kernel 6: Out(256,4096) = W_w(256,128) @ Yview(128,4096) + W_b + x
// grid (32, 2, 4)
// ---------------------------------------------------------------------------
__global__ __launch_bounds__(256, 2) void out_kernel(
    const float* __restrict__ x,
    const float* __restrict__ Ww, const float* __restrict__ Wb,
    float* __restrict__ out)
{
    int b = blockIdx.z;
    const float* Byc = g_Y + (size_t)b * CB * NSP;   // (128,4096) flat view, ld=4096
    const float* xb  = x + (size_t)b * CIN * NSP;
    float* Cb_ = out + (size_t)b * CIN * NSP;

    __shared__ __align__(16) float As[8][132];
    __shared__ __align__(16) float Bs[8][128];
    int tid  = threadIdx.x;
    int aRow = tid >> 1, aCol = (tid & 1) << 2;
    int bRow = tid >> 5, bCol = (tid & 31) << 2;
    int ty = tid >> 4, tx = tid & 15;
    int rowBase = blockIdx.y << 7;
    int colBase = blockIdx.x << 7;

    u64 acc[8][4];
#pragma unroll
    for (int i = 0; i < 8; i++)
#pragma unroll
        for (int jp = 0; jp < 4; jp++) acc[i][jp] = pk2(0.f, 0.f);

    for (int k0 = 0; k0 < CB; k0 += 8) {
        float4 av = *(const float4*)(Ww + (size_t)(rowBase + aRow) * CB + k0 + aCol);
        As[aCol + 0][aRow] = av.x;
        As[aCol + 1][aRow] = av.y;
        As[aCol + 2][aRow] = av.z;
        As[aCol + 3][aRow] = av.w;
        *(float4*)&Bs[bRow][bCol] =
            *(const float4*)(Byc + (size_t)(k0 + bRow) * NSP + colBase + bCol);
        __syncthreads();
#pragma unroll
        for (int k = 0; k < 8; k++) {
            float ra[8];
            *(float4*)(ra)     = *(const float4*)&As[k][ty << 2];
            *(float4*)(ra + 4) = *(const float4*)&As[k][64 + (ty << 2)];
            const u64* bp0 = (const u64*)&Bs[k][tx << 2];
            const u64* bp1 = (const u64*)&Bs[k][64 + (tx << 2)];
            u64 rb[4] = {bp0[0], bp0[1], bp1[0], bp1[1]};
#pragma unroll
            for (int i = 0; i < 8; i++) {
                u64 aa = pk2(ra[i], ra[i]);
#pragma unroll
                for (int jp = 0; jp < 4; jp++)
                    acc[i][jp] = fma2(aa, rb[jp], acc[i][jp]);
            }
        }
        __syncthreads();
    }
#pragma unroll
    for (int i = 0; i < 8; i++) {
        int row = rowBase + ((i >> 2) << 6) + (ty << 2) + (i & 3);
        float bv = Wb[row];
#pragma unroll
        for (int jh = 0; jh < 2; jh++) {
            int col = colBase + (jh << 6) + (tx << 2);
            float4 xv = *(const float4*)(xb + (size_t)row * NSP + col);
            float4 v;
            upk2(acc[i][2 * jh],     v.x, v.y);
            upk2(acc[i][2 * jh + 1], v.z, v.w);
            v.x += bv + xv.x; v.y += bv + xv.y;
            v.z += bv + xv.z; v.w += bv + xv.w;
            *(float4*)(Cb_ + (size_t)row * NSP + col) = v;
        }
    }
}

// ---------------------------------------------------------------------------
extern "C" void kernel_launch(void* const* d_in, const int* in_sizes, int n_in,
                              void* d_out, int out_size)
{
    const float* x  = (const float*)d_in[0];
    const float* tw = (const float*)d_in[1];
    const float* tb = (const float*)d_in[2];
    const float* pw = (const float*)d_in[3];
    const float* pb = (const float*)d_in[4];
    const float* gw = (const float*)d_in[5];
    const float* gb = (const float*)d_in[6];
    const float* Ww = (const float*)d_in[7];
    const float* Wb = (const float*)d_in[8];
    float* out = (float*)d_out;

    conv_tpg_kernel<<<dim3(32, 1, 12), 256>>>(x, tw, tb, pw, pb, gw, gb);
    scores_kernel<<<dim3(32, 32, 4), 256>>>();
    zreduce_kernel<<<64, 256>>>();
    y_kernel<<<dim3(KSPLIT, 32, 4), 256>>>();
    yreduce_kernel<<<2048, 256>>>();
    out_kernel<<<dim3(32, 2, 4), 256>>>(x, Ww, Wb, out);
}